// round 3
// baseline (speedup 1.0000x reference)
#include <cuda_runtime.h>

#define BATCH 512
#define DLAT  32
#define ACT   18
#define FED   128
#define AED   64
#define VD    192
#define KDIM  192
#define HID   256
#define NH    32

// ---------------- scratch (static device allocations only) ----------------
__device__ float g_w[BATCH * DLAT];                    // softmax weights [b][d]
__device__ float g_ae[BATCH * AED];                    // action embeds  [b][j]
__device__ float g_G[NH * DLAT * HID];                 // [h][d][k]
__device__ float g_c0[NH * HID];                       // [h][k]
__device__ float g_pooled[(size_t)NH * BATCH * HID];   // [h][b][k]  16MB

// ============================================================================
// K1: per-batch prep: queries, action embeds, scores, softmax, attn_weights
// grid = B blocks, 192 threads
// ============================================================================
__global__ void k_prep(const float* __restrict__ feat, const float* __restrict__ act,
                       const float* __restrict__ Wq,   const float* __restrict__ bq,
                       const float* __restrict__ Wk,   const float* __restrict__ bk,
                       const float* __restrict__ Wav,  const float* __restrict__ bav,
                       float* __restrict__ out_attnw)
{
    int b = blockIdx.x;
    int t = threadIdx.x;
    __shared__ float a_s[ACT];
    __shared__ float q_s[KDIM];
    __shared__ float s1_s[DLAT];
    __shared__ float w_s[DLAT];
    __shared__ float s0_s;

    if (t < ACT) a_s[t] = act[b * ACT + t];
    __syncthreads();

    // queries[b,t] = a @ Wq + bq   (t < 192 always, blockDim=192)
    float q = bq[t];
#pragma unroll
    for (int i = 0; i < ACT; i++) q = fmaf(a_s[i], Wq[i * KDIM + t], q);
    q_s[t] = q;

    // action embeds (t < 64)
    if (t < AED) {
        float e = bav[t];
#pragma unroll
        for (int i = 0; i < ACT; i++) e = fmaf(a_s[i], Wav[i * AED + t], e);
        g_ae[b * AED + t] = e;
    }
    __syncthreads();

    // s1[d] = Wk[d,:] . q  ;  s0 = bk . q
    if (t < DLAT) {
        const float* wk = Wk + t * KDIM;
        float s = 0.f;
        for (int j = 0; j < KDIM; j++) s = fmaf(wk[j], q_s[j], s);
        s1_s[t] = s;
    } else if (t == DLAT) {
        float s = 0.f;
        for (int j = 0; j < KDIM; j++) s = fmaf(bk[j], q_s[j], s);
        s0_s = s;
    }
    __syncthreads();

    // softmax over d (warp 0)
    if (t < 32) {
        const float inv = 0.07216878364870323f; // 1/sqrt(192)
        float sc = (feat[b * DLAT + t] * s1_s[t] + s0_s) * inv;
        float m = sc;
#pragma unroll
        for (int o = 16; o > 0; o >>= 1) m = fmaxf(m, __shfl_xor_sync(0xffffffffu, m, o));
        float e = __expf(sc - m);
        float s = e;
#pragma unroll
        for (int o = 16; o > 0; o >>= 1) s += __shfl_xor_sync(0xffffffffu, s, o);
        float w = e / s;
        w_s[t] = w;
        g_w[b * DLAT + t] = w;
    }
    __syncthreads();

    // attn_weights[b,h,d] = w[b,d] broadcast over h
    for (int idx = t; idx < NH * DLAT; idx += blockDim.x)
        out_attnw[(size_t)b * NH * DLAT + idx] = w_s[idx & (DLAT - 1)];
}

// ============================================================================
// K2: precompute G[h,d,k] = Wfv[d,:] @ W1[h,:128,k]   and
//                c0[h,k]  = bfv @ W1[h,:128,k] + b1[h,k]
// grid = (2 k-chunks of 128, NH), 256 threads
// ============================================================================
__global__ __launch_bounds__(256)
void k_gpre(const float* __restrict__ Wfv, const float* __restrict__ bfv,
            const float* __restrict__ W1,  const float* __restrict__ b1)
{
    int h = blockIdx.y;
    int kbase = blockIdx.x * 128;
    int t = threadIdx.x;

    extern __shared__ float sm2[];
    float* W1s   = sm2;                 // [128 f][128 kk]
    float* Wfv_s = W1s + FED * 128;     // [32 d][128 f]
    float* bfv_s = Wfv_s + DLAT * FED;  // [128]

    const float* W1h = W1 + (size_t)h * VD * HID;
    for (int idx = t; idx < FED * 128; idx += 256) {
        int f = idx >> 7, kk = idx & 127;
        W1s[f * 128 + kk] = W1h[f * HID + kbase + kk];
    }
    for (int idx = t; idx < DLAT * FED; idx += 256) Wfv_s[idx] = Wfv[idx];
    if (t < FED) bfv_s[t] = bfv[t];
    __syncthreads();

    int ty = t >> 5, tx = t & 31;
    int d0 = ty * 4;
    float acc[4][4] = {};
    for (int f = 0; f < FED; f++) {
        float w1r[4];
#pragma unroll
        for (int i = 0; i < 4; i++) w1r[i] = W1s[f * 128 + tx + 32 * i];
#pragma unroll
        for (int jj = 0; jj < 4; jj++) {
            float wv = Wfv_s[(d0 + jj) * FED + f];
#pragma unroll
            for (int i = 0; i < 4; i++) acc[jj][i] = fmaf(wv, w1r[i], acc[jj][i]);
        }
    }
#pragma unroll
    for (int jj = 0; jj < 4; jj++)
#pragma unroll
        for (int i = 0; i < 4; i++)
            g_G[((size_t)h * DLAT + d0 + jj) * HID + kbase + tx + 32 * i] = acc[jj][i];

    if (t < 128) {
        float c = b1[h * HID + kbase + t];
        for (int f = 0; f < FED; f++) c = fmaf(bfv_s[f], W1s[f * 128 + t], c);
        g_c0[h * HID + kbase + t] = c;
    }
}

// ============================================================================
// K4: pooled[h,b,k] = sum_d w[b,d] * relu( z[b,d]*G[h,d,k] + E[b,k] + c0[h,k] )
//     with E[b,k] = ae[b,:] @ W1[h,128:,k] computed in-block
// grid = (B/64, NH), 256 threads; each thread computes 8b x 8k outputs
// ============================================================================
#define BT4 64
__global__ __launch_bounds__(256)
void k_pool(const float* __restrict__ feat, const float* __restrict__ W1)
{
    int h  = blockIdx.y;
    int b0 = blockIdx.x * BT4;
    int t  = threadIdx.x;

    extern __shared__ float sm4[];
    float* G_s   = sm4;                  // 32*256
    float* c0_s  = G_s + DLAT * HID;     // 256
    float* W1a_s = c0_s + HID;           // 64*256
    float* ae_s  = W1a_s + AED * HID;    // 64*64
    float* z_s   = ae_s + BT4 * AED;     // 64*32
    float* w_s   = z_s + BT4 * DLAT;     // 64*32

    const float* W1ha = W1 + (size_t)h * VD * HID + (size_t)FED * HID;
    for (int idx = t; idx < DLAT * HID; idx += 256) G_s[idx] = g_G[(size_t)h * DLAT * HID + idx];
    for (int idx = t; idx < HID;        idx += 256) c0_s[idx] = g_c0[h * HID + idx];
    for (int idx = t; idx < AED * HID;  idx += 256) W1a_s[idx] = W1ha[idx];
    for (int idx = t; idx < BT4 * AED;  idx += 256) ae_s[idx] = g_ae[b0 * AED + idx];
    for (int idx = t; idx < BT4 * DLAT; idx += 256) z_s[idx]  = feat[b0 * DLAT + idx];
    for (int idx = t; idx < BT4 * DLAT; idx += 256) w_s[idx]  = g_w[b0 * DLAT + idx];
    __syncthreads();

    int tb = t >> 5, tk = t & 31;

    // e0 = E + c0
    float e0[8][8];
#pragma unroll
    for (int r = 0; r < 8; r++)
#pragma unroll
        for (int i = 0; i < 8; i++) e0[r][i] = c0_s[tk + 32 * i];

    for (int a = 0; a < AED; a++) {
        float w1a[8];
#pragma unroll
        for (int i = 0; i < 8; i++) w1a[i] = W1a_s[a * HID + tk + 32 * i];
#pragma unroll
        for (int r = 0; r < 8; r++) {
            float av = ae_s[(tb * 8 + r) * AED + a];
#pragma unroll
            for (int i = 0; i < 8; i++) e0[r][i] = fmaf(av, w1a[i], e0[r][i]);
        }
    }

    float acc[8][8] = {};
    for (int d = 0; d < DLAT; d++) {
        float gr[8];
#pragma unroll
        for (int i = 0; i < 8; i++) gr[i] = G_s[d * HID + tk + 32 * i];
#pragma unroll
        for (int r = 0; r < 8; r++) {
            float zz = z_s[(tb * 8 + r) * DLAT + d];
            float ww = w_s[(tb * 8 + r) * DLAT + d];
#pragma unroll
            for (int i = 0; i < 8; i++) {
                float v = fmaxf(fmaf(zz, gr[i], e0[r][i]), 0.f);
                acc[r][i] = fmaf(ww, v, acc[r][i]);
            }
        }
    }

    float* outp = g_pooled + (size_t)h * BATCH * HID + (size_t)b0 * HID;
#pragma unroll
    for (int r = 0; r < 8; r++)
#pragma unroll
        for (int i = 0; i < 8; i++)
            outp[(tb * 8 + r) * HID + tk + 32 * i] = acc[r][i];
}

// ============================================================================
// K5: attn_out = pooled @ W2 + b2 ; h2 = relu(attn_out @ W1o + b1o)
//     effect[b,h] = h2 . W2o[h] + b2o[h]
// grid = (B/64, NH), 256 threads (16x16), register-tiled GEMMs
// ============================================================================
#define BT5 64
__global__ __launch_bounds__(256)
void k_out(const float* __restrict__ W2,  const float* __restrict__ b2,
           const float* __restrict__ W1o, const float* __restrict__ b1o,
           const float* __restrict__ W2o, const float* __restrict__ b2o,
           float* __restrict__ effect)
{
    int h  = blockIdx.y;
    int b0 = blockIdx.x * BT5;
    int t  = threadIdx.x;

    extern __shared__ float sm5[];
    const int PSTR = HID + 1;                 // 257 (pad vs bank conflicts)
    float* P_s  = sm5;                        // pooled [64][257], reused for W1o chunks
    float* BUF  = P_s + BT5 * PSTR;           // W2 chunks [64][192] / attn_out [64][193]
    const int BUFSZ = 64 * 193;
    float* b2_s  = BUF + BUFSZ;               // 192
    float* b1o_s = b2_s + VD;                 // 256
    float* W2o_s = b1o_s + HID;               // 256

    const float* pin = g_pooled + (size_t)h * BATCH * HID + (size_t)b0 * HID;
    for (int idx = t; idx < BT5 * HID; idx += 256) {
        int bb = idx >> 8, k = idx & 255;
        P_s[bb * PSTR + k] = pin[idx];
    }
    for (int idx = t; idx < VD;  idx += 256) b2_s[idx] = b2[h * VD + idx];
    for (int idx = t; idx < HID; idx += 256) { b1o_s[idx] = b1o[h * HID + idx]; W2o_s[idx] = W2o[h * HID + idx]; }

    int ty = t >> 4, tx = t & 15;

    // ---- Stage B: attn_out[64][192] = P @ W2[h], k-chunked through smem ----
    float acc1[4][12] = {};
    const float* W2h = W2 + (size_t)h * HID * VD;
    for (int kc = 0; kc < 4; kc++) {
        __syncthreads();
        for (int idx = t; idx < 64 * VD; idx += 256)
            BUF[idx] = W2h[kc * 64 * VD + idx];           // [kk][v], stride 192
        __syncthreads();
#pragma unroll 4
        for (int kk = 0; kk < 64; kk++) {
            float p[4];
#pragma unroll
            for (int r = 0; r < 4; r++) p[r] = P_s[(ty * 4 + r) * PSTR + kc * 64 + kk];
            float w2r[12];
#pragma unroll
            for (int j = 0; j < 12; j++) w2r[j] = BUF[kk * VD + tx + 16 * j];
#pragma unroll
            for (int r = 0; r < 4; r++)
#pragma unroll
                for (int j = 0; j < 12; j++)
                    acc1[r][j] = fmaf(p[r], w2r[j], acc1[r][j]);
        }
    }
    __syncthreads();
    // attn_out (+b2) into BUF [bb][v] stride 193
#pragma unroll
    for (int r = 0; r < 4; r++)
#pragma unroll
        for (int j = 0; j < 12; j++)
            BUF[(ty * 4 + r) * 193 + tx + 16 * j] = acc1[r][j] + b2_s[tx + 16 * j];
    __syncthreads();

    // ---- Stage C: h2 = relu(attn_out @ W1o + b1o); effect = h2 . W2o ----
    float acc2[4][16] = {};
    const float* W1oh = W1o + (size_t)h * VD * HID;
    for (int vc = 0; vc < 4; vc++) {
        __syncthreads();
        for (int idx = t; idx < 48 * HID; idx += 256)
            P_s[idx] = W1oh[vc * 48 * HID + idx];         // [vv][k], stride 256
        __syncthreads();
#pragma unroll 2
        for (int vv = 0; vv < 48; vv++) {
            float av[4];
#pragma unroll
            for (int r = 0; r < 4; r++) av[r] = BUF[(ty * 4 + r) * 193 + vc * 48 + vv];
            float w1r[16];
#pragma unroll
            for (int j = 0; j < 16; j++) w1r[j] = P_s[vv * HID + tx + 16 * j];
#pragma unroll
            for (int r = 0; r < 4; r++)
#pragma unroll
                for (int j = 0; j < 16; j++)
                    acc2[r][j] = fmaf(av[r], w1r[j], acc2[r][j]);
        }
    }

    float part[4];
#pragma unroll
    for (int r = 0; r < 4; r++) {
        float s = 0.f;
#pragma unroll
        for (int j = 0; j < 16; j++) {
            int k = tx + 16 * j;
            float hv = fmaxf(acc2[r][j] + b1o_s[k], 0.f);
            s = fmaf(hv, W2o_s[k], s);
        }
        part[r] = s;
    }
#pragma unroll
    for (int o = 8; o > 0; o >>= 1)
#pragma unroll
        for (int r = 0; r < 4; r++)
            part[r] += __shfl_xor_sync(0xffffffffu, part[r], o);

    if (tx == 0) {
        float bo = b2o[h];
#pragma unroll
        for (int r = 0; r < 4; r++)
            effect[(size_t)(b0 + ty * 4 + r) * NH + h] = part[r] + bo;
    }
}

// ============================================================================
extern "C" void kernel_launch(void* const* d_in, const int* in_sizes, int n_in,
                              void* d_out, int out_size)
{
    const float* feat = (const float*)d_in[0];
    const float* act  = (const float*)d_in[1];
    const float* Wq   = (const float*)d_in[2];
    const float* bq   = (const float*)d_in[3];
    const float* Wk   = (const float*)d_in[4];
    const float* bk   = (const float*)d_in[5];
    const float* Wav  = (const float*)d_in[6];
    const float* bav  = (const float*)d_in[7];
    const float* Wfv  = (const float*)d_in[8];
    const float* bfv  = (const float*)d_in[9];
    const float* W1   = (const float*)d_in[10];
    const float* b1   = (const float*)d_in[11];
    const float* W2   = (const float*)d_in[12];
    const float* b2   = (const float*)d_in[13];
    const float* W1o  = (const float*)d_in[14];
    const float* b1o  = (const float*)d_in[15];
    const float* W2o  = (const float*)d_in[16];
    const float* b2o  = (const float*)d_in[17];

    float* out    = (float*)d_out;
    float* effect = out;                    // [B, H]
    float* attnw  = out + BATCH * NH;       // [B, H, D]

    int smem2 = (FED * 128 + DLAT * FED + FED) * 4;
    int smem4 = (DLAT * HID + HID + AED * HID + BT4 * AED + 2 * BT4 * DLAT) * 4;
    int smem5 = (BT5 * (HID + 1) + 64 * 193 + VD + HID + HID) * 4;
    cudaFuncSetAttribute(k_gpre, cudaFuncAttributeMaxDynamicSharedMemorySize, smem2);
    cudaFuncSetAttribute(k_pool, cudaFuncAttributeMaxDynamicSharedMemorySize, smem4);
    cudaFuncSetAttribute(k_out,  cudaFuncAttributeMaxDynamicSharedMemorySize, smem5);

    k_prep<<<BATCH, 192>>>(feat, act, Wq, bq, Wk, bk, Wav, bav, attnw);
    k_gpre<<<dim3(2, NH), 256, smem2>>>(Wfv, bfv, W1, b1);
    k_pool<<<dim3(BATCH / BT4, NH), 256, smem4>>>(feat, W1);
    k_out <<<dim3(BATCH / BT5, NH), 256, smem5>>>(W2, b2, W1o, b1o, W2o, b2o, effect);
}

// round 4
// speedup vs baseline: 1.3382x; 1.3382x over previous
#include <cuda_runtime.h>

#define BATCH 512
#define DLAT  32
#define ACT   18
#define FED   128
#define AED   64
#define VD    192
#define KDIM  192
#define HID   256
#define NH    32

// ---------------- scratch (static device allocations only) ----------------
__device__ __align__(16) float g_w[BATCH * DLAT];
__device__ __align__(16) float g_ae[BATCH * AED];
__device__ __align__(16) float g_G[NH * DLAT * HID];
__device__ __align__(16) float g_c0[NH * HID];
__device__ __align__(16) float g_pooled[(size_t)NH * BATCH * HID];   // 16MB
__device__ __align__(16) float g_M[(size_t)NH * HID * HID];          // 8MB: W2@W1o per head
__device__ __align__(16) float g_c1[NH * HID];                       // b2@W1o + b1o

// ---------------- packed f32x2 helpers ----------------
union F2 { float2 f; unsigned long long u; };

__device__ __forceinline__ F2 ffma2(F2 a, F2 b, F2 c) {
    F2 d;
    asm("fma.rn.f32x2 %0, %1, %2, %3;" : "=l"(d.u) : "l"(a.u), "l"(b.u), "l"(c.u));
    return d;
}
__device__ __forceinline__ F2 bcast2(float x) { F2 r; r.f.x = x; r.f.y = x; return r; }
__device__ __forceinline__ F2 lds2(const float* p) { F2 r; r.u = *(const unsigned long long*)p; return r; }
__device__ __forceinline__ F2 zero2() { F2 r; r.f.x = 0.f; r.f.y = 0.f; return r; }

// ============================================================================
// K1: queries, action embeds, scores, softmax, attn_weights.  grid=B, 192 thr
// ============================================================================
__global__ void k_prep(const float* __restrict__ feat, const float* __restrict__ act,
                       const float* __restrict__ Wq,   const float* __restrict__ bq,
                       const float* __restrict__ Wk,   const float* __restrict__ bk,
                       const float* __restrict__ Wav,  const float* __restrict__ bav,
                       float* __restrict__ out_attnw)
{
    int b = blockIdx.x;
    int t = threadIdx.x;
    __shared__ float a_s[ACT];
    __shared__ float q_s[KDIM];
    __shared__ float s1_s[DLAT];
    __shared__ float w_s[DLAT];
    __shared__ float s0_s;

    if (t < ACT) a_s[t] = act[b * ACT + t];
    __syncthreads();

    float q = bq[t];
#pragma unroll
    for (int i = 0; i < ACT; i++) q = fmaf(a_s[i], Wq[i * KDIM + t], q);
    q_s[t] = q;

    if (t < AED) {
        float e = bav[t];
#pragma unroll
        for (int i = 0; i < ACT; i++) e = fmaf(a_s[i], Wav[i * AED + t], e);
        g_ae[b * AED + t] = e;
    }
    __syncthreads();

    if (t < DLAT) {
        const float* wk = Wk + t * KDIM;
        float s = 0.f;
        for (int j = 0; j < KDIM; j++) s = fmaf(wk[j], q_s[j], s);
        s1_s[t] = s;
    } else if (t == DLAT) {
        float s = 0.f;
        for (int j = 0; j < KDIM; j++) s = fmaf(bk[j], q_s[j], s);
        s0_s = s;
    }
    __syncthreads();

    if (t < 32) {
        const float inv = 0.07216878364870323f; // 1/sqrt(192)
        float sc = (feat[b * DLAT + t] * s1_s[t] + s0_s) * inv;
        float m = sc;
#pragma unroll
        for (int o = 16; o > 0; o >>= 1) m = fmaxf(m, __shfl_xor_sync(0xffffffffu, m, o));
        float e = __expf(sc - m);
        float s = e;
#pragma unroll
        for (int o = 16; o > 0; o >>= 1) s += __shfl_xor_sync(0xffffffffu, s, o);
        float w = e / s;
        w_s[t] = w;
        g_w[b * DLAT + t] = w;
    }
    __syncthreads();

    for (int idx = t; idx < NH * DLAT; idx += blockDim.x)
        out_attnw[(size_t)b * NH * DLAT + idx] = w_s[idx & (DLAT - 1)];
}

// ============================================================================
// K2: G[h,d,k] = Wfv[d,:] @ W1[h,:128,k],  c0[h,k] = bfv @ W1[h,:128,k] + b1
// grid = (2, NH), 256 threads
// ============================================================================
__global__ __launch_bounds__(256)
void k_gpre(const float* __restrict__ Wfv, const float* __restrict__ bfv,
            const float* __restrict__ W1,  const float* __restrict__ b1)
{
    int h = blockIdx.y;
    int kbase = blockIdx.x * 128;
    int t = threadIdx.x;

    extern __shared__ float sm2[];
    float* W1s   = sm2;                 // [128 f][128 kk]
    float* Wfv_s = W1s + FED * 128;     // [32 d][128 f]
    float* bfv_s = Wfv_s + DLAT * FED;  // [128]

    const float* W1h = W1 + (size_t)h * VD * HID;
    for (int idx = t; idx < FED * 128; idx += 256) {
        int f = idx >> 7, kk = idx & 127;
        W1s[f * 128 + kk] = W1h[f * HID + kbase + kk];
    }
    for (int idx = t; idx < DLAT * FED; idx += 256) Wfv_s[idx] = Wfv[idx];
    if (t < FED) bfv_s[t] = bfv[t];
    __syncthreads();

    int ty = t >> 5, tx = t & 31;
    int d0 = ty * 4;
    float acc[4][4] = {};
    for (int f = 0; f < FED; f++) {
        float w1r[4];
#pragma unroll
        for (int i = 0; i < 4; i++) w1r[i] = W1s[f * 128 + tx + 32 * i];
#pragma unroll
        for (int jj = 0; jj < 4; jj++) {
            float wv = Wfv_s[(d0 + jj) * FED + f];
#pragma unroll
            for (int i = 0; i < 4; i++) acc[jj][i] = fmaf(wv, w1r[i], acc[jj][i]);
        }
    }
#pragma unroll
    for (int jj = 0; jj < 4; jj++)
#pragma unroll
        for (int i = 0; i < 4; i++)
            g_G[((size_t)h * DLAT + d0 + jj) * HID + kbase + tx + 32 * i] = acc[jj][i];

    if (t < 128) {
        float c = b1[h * HID + kbase + t];
        for (int f = 0; f < FED; f++) c = fmaf(bfv_s[f], W1s[f * 128 + t], c);
        g_c0[h * HID + kbase + t] = c;
    }
}

// ============================================================================
// K3: M[h] = W2[h] @ W1o[h]   [256,192]@[192,256]
//     c1[h,k'] = b2[h] @ W1o[h] + b1o[h]
// grid = (2 kblk, 2 cblk, NH), 256 threads, f32x2 register tiles 8x(4 pairs)
// ============================================================================
__global__ __launch_bounds__(256)
void k_mpre(const float* __restrict__ W2, const float* __restrict__ W1o,
            const float* __restrict__ b2, const float* __restrict__ b1o)
{
    int h  = blockIdx.z;
    int kb = blockIdx.x * 128;   // M row block (pooled-k dim)
    int cb = blockIdx.y * 128;   // M col block (k' dim)
    int t  = threadIdx.x;

    extern __shared__ float sm3[];
    float* As = sm3;             // [128][33]
    float* Bs = As + 128 * 33;   // [32][132]

    const float* Ap = W2  + (size_t)h * HID * VD;   // [k][v]  stride VD
    const float* Bp = W1o + (size_t)h * VD * HID;   // [v][k'] stride HID

    int ty = t >> 4, tx = t & 15;
    F2 acc[8][4];
#pragma unroll
    for (int r = 0; r < 8; r++)
#pragma unroll
        for (int j = 0; j < 4; j++) acc[r][j] = zero2();

    for (int vc = 0; vc < VD; vc += 32) {
        __syncthreads();
        {
            int row = t >> 5, col = t & 31;
#pragma unroll
            for (int rr = 0; rr < 16; rr++)
                As[(row + rr * 8) * 33 + col] = Ap[(size_t)(kb + row + rr * 8) * VD + vc + col];
        }
#pragma unroll
        for (int i = 0; i < 16; i++) {
            int idx = t + i * 256;
            int vr = idx >> 7, col = idx & 127;
            Bs[vr * 132 + col] = Bp[(size_t)(vc + vr) * HID + cb + col];
        }
        __syncthreads();
#pragma unroll
        for (int v = 0; v < 32; v++) {
            F2 bvec[4];
#pragma unroll
            for (int j = 0; j < 4; j++) bvec[j] = lds2(&Bs[v * 132 + tx * 2 + 32 * j]);
#pragma unroll
            for (int r = 0; r < 8; r++) {
                F2 a2 = bcast2(As[(ty * 8 + r) * 33 + v]);
#pragma unroll
                for (int j = 0; j < 4; j++) acc[r][j] = ffma2(a2, bvec[j], acc[r][j]);
            }
        }
    }

    float* Mp = g_M + (size_t)h * HID * HID;
#pragma unroll
    for (int r = 0; r < 8; r++)
#pragma unroll
        for (int j = 0; j < 4; j++)
            *(unsigned long long*)&Mp[(size_t)(kb + ty * 8 + r) * HID + cb + tx * 2 + 32 * j] = acc[r][j].u;

    if (blockIdx.x == 0 && t < 128) {
        int kp = cb + t;
        float c = b1o[h * HID + kp];
        for (int v = 0; v < VD; v++)
            c = fmaf(b2[h * VD + v], Bp[(size_t)v * HID + kp], c);
        g_c1[h * HID + kp] = c;
    }
}

// ============================================================================
// K4: pooled[h,b,k] = sum_d w[b,d]*relu( z[b,d]*G[h,d,k] + E[b,k] + c0[h,k] )
//     E[b,k] = ae[b,:] @ W1[h,128:,k].  f32x2 tiles: 8 rows x 4 col-pairs.
// grid = (B/64, NH), 256 threads
// ============================================================================
#define BT4 64
__global__ __launch_bounds__(256)
void k_pool(const float* __restrict__ feat, const float* __restrict__ W1)
{
    int h  = blockIdx.y;
    int b0 = blockIdx.x * BT4;
    int t  = threadIdx.x;

    extern __shared__ float sm4[];
    float* G_s   = sm4;                  // 32*256
    float* c0_s  = G_s + DLAT * HID;     // 256
    float* W1a_s = c0_s + HID;           // 64*256
    float* ae_s  = W1a_s + AED * HID;    // 64*64
    float* z_s   = ae_s + BT4 * AED;     // 64*32
    float* w_s   = z_s + BT4 * DLAT;     // 64*32

    const float* W1ha = W1 + (size_t)h * VD * HID + (size_t)FED * HID;
    for (int idx = t; idx < DLAT * HID; idx += 256) G_s[idx] = g_G[(size_t)h * DLAT * HID + idx];
    for (int idx = t; idx < HID;        idx += 256) c0_s[idx] = g_c0[h * HID + idx];
    for (int idx = t; idx < AED * HID;  idx += 256) W1a_s[idx] = W1ha[idx];
    for (int idx = t; idx < BT4 * AED;  idx += 256) ae_s[idx] = g_ae[b0 * AED + idx];
    for (int idx = t; idx < BT4 * DLAT; idx += 256) z_s[idx]  = feat[b0 * DLAT + idx];
    for (int idx = t; idx < BT4 * DLAT; idx += 256) w_s[idx]  = g_w[b0 * DLAT + idx];
    __syncthreads();

    int tb = t >> 5, tk = t & 31;   // cols: pairs at tk*2 + 64*i

    F2 e0[8][4];
#pragma unroll
    for (int i = 0; i < 4; i++) {
        F2 c = lds2(&c0_s[tk * 2 + 64 * i]);
#pragma unroll
        for (int r = 0; r < 8; r++) e0[r][i] = c;
    }

    for (int a = 0; a < AED; a++) {
        F2 w1a[4];
#pragma unroll
        for (int i = 0; i < 4; i++) w1a[i] = lds2(&W1a_s[a * HID + tk * 2 + 64 * i]);
#pragma unroll
        for (int r = 0; r < 8; r++) {
            F2 av = bcast2(ae_s[(tb * 8 + r) * AED + a]);
#pragma unroll
            for (int i = 0; i < 4; i++) e0[r][i] = ffma2(av, w1a[i], e0[r][i]);
        }
    }

    F2 acc[8][4];
#pragma unroll
    for (int r = 0; r < 8; r++)
#pragma unroll
        for (int i = 0; i < 4; i++) acc[r][i] = zero2();

    for (int d = 0; d < DLAT; d++) {
        F2 gr[4];
#pragma unroll
        for (int i = 0; i < 4; i++) gr[i] = lds2(&G_s[d * HID + tk * 2 + 64 * i]);
#pragma unroll
        for (int r = 0; r < 8; r++) {
            F2 z2 = bcast2(z_s[(tb * 8 + r) * DLAT + d]);
            F2 w2 = bcast2(w_s[(tb * 8 + r) * DLAT + d]);
#pragma unroll
            for (int i = 0; i < 4; i++) {
                F2 u = ffma2(z2, gr[i], e0[r][i]);
                u.f.x = fmaxf(u.f.x, 0.f);
                u.f.y = fmaxf(u.f.y, 0.f);
                acc[r][i] = ffma2(w2, u, acc[r][i]);
            }
        }
    }

    float* outp = g_pooled + (size_t)h * BATCH * HID + (size_t)b0 * HID;
#pragma unroll
    for (int r = 0; r < 8; r++)
#pragma unroll
        for (int i = 0; i < 4; i++)
            *(unsigned long long*)&outp[(tb * 8 + r) * HID + tk * 2 + 64 * i] = acc[r][i].u;
}

// ============================================================================
// K5: h2 = relu(pooled @ M[h] + c1[h]);  effect[b,h] = h2 . W2o[h] + b2o[h]
// grid = (B/64, NH) = 256 blocks, 256 threads, 2 CTAs/SM, double-buffered M.
// Thread tile: 4 rows x 8 col-pairs (f32x2).
// ============================================================================
#define KC 16
__global__ __launch_bounds__(256, 2)
void k_out(const float* __restrict__ W2o, const float* __restrict__ b2o,
           float* __restrict__ effect)
{
    int h  = blockIdx.y;
    int b0 = blockIdx.x * 64;
    int t  = threadIdx.x;

    extern __shared__ float sm5[];
    const int PST = 260;                 // pad: 260*4 % 16 == 0 for float4 stores
    float* P_s   = sm5;                  // [64][260]
    float* Mb    = P_s + 64 * PST;       // [2][KC][256]
    float* c1_s  = Mb + 2 * KC * HID;    // 256
    float* W2o_s = c1_s + HID;           // 256

    const float* pin = g_pooled + (size_t)h * BATCH * HID + (size_t)b0 * HID;
    for (int idx = t; idx < 64 * 64; idx += 256) {          // 4096 float4
        int row = idx >> 6, c4 = idx & 63;
        *(float4*)&P_s[row * PST + c4 * 4] = *(const float4*)&pin[row * HID + c4 * 4];
    }
    for (int idx = t; idx < HID; idx += 256) {
        c1_s[idx]  = g_c1[h * HID + idx];
        W2o_s[idx] = W2o[h * HID + idx];
    }
    const float* Mp = g_M + (size_t)h * HID * HID;
    for (int idx = t; idx < KC * 64; idx += 256) {          // chunk 0: 1024 float4
        int r = idx >> 6, c4 = idx & 63;
        *(float4*)&Mb[r * HID + c4 * 4] = *(const float4*)&Mp[(size_t)r * HID + c4 * 4];
    }
    __syncthreads();

    int ty = t >> 4, tx = t & 15;

    F2 acc[4][8];
#pragma unroll
    for (int r = 0; r < 4; r++)
#pragma unroll
        for (int j = 0; j < 8; j++) acc[r][j] = zero2();

    for (int kc = 0; kc < HID / KC; kc++) {
        float4 pf[4];
        if (kc + 1 < HID / KC) {
#pragma unroll
            for (int i = 0; i < 4; i++) {
                int idx = t + i * 256;
                int r = idx >> 6, c4 = idx & 63;
                pf[i] = *(const float4*)&Mp[(size_t)((kc + 1) * KC + r) * HID + c4 * 4];
            }
        }
        const float* Mc = Mb + (kc & 1) * KC * HID;
#pragma unroll
        for (int kk = 0; kk < KC; kk++) {
            int k = kc * KC + kk;
            F2 mv[8];
#pragma unroll
            for (int j = 0; j < 8; j++) mv[j] = lds2(&Mc[kk * HID + tx * 2 + 32 * j]);
#pragma unroll
            for (int r = 0; r < 4; r++) {
                F2 p2 = bcast2(P_s[(ty * 4 + r) * PST + k]);
#pragma unroll
                for (int j = 0; j < 8; j++) acc[r][j] = ffma2(p2, mv[j], acc[r][j]);
            }
        }
        if (kc + 1 < HID / KC) {
            float* dst = Mb + ((kc + 1) & 1) * KC * HID;
#pragma unroll
            for (int i = 0; i < 4; i++) {
                int idx = t + i * 256;
                int r = idx >> 6, c4 = idx & 63;
                *(float4*)&dst[r * HID + c4 * 4] = pf[i];
            }
        }
        __syncthreads();
    }

    // epilogue: +c1, relu, dot W2o, reduce over tx
    float part[4];
#pragma unroll
    for (int r = 0; r < 4; r++) {
        float s = 0.f;
#pragma unroll
        for (int j = 0; j < 8; j++) {
            int c = tx * 2 + 32 * j;
            float hx = fmaxf(acc[r][j].f.x + c1_s[c], 0.f);
            float hy = fmaxf(acc[r][j].f.y + c1_s[c + 1], 0.f);
            s = fmaf(hx, W2o_s[c], s);
            s = fmaf(hy, W2o_s[c + 1], s);
        }
        part[r] = s;
    }
#pragma unroll
    for (int o = 8; o > 0; o >>= 1)
#pragma unroll
        for (int r = 0; r < 4; r++)
            part[r] += __shfl_xor_sync(0xffffffffu, part[r], o);

    if (tx == 0) {
        float bo = b2o[h];
#pragma unroll
        for (int r = 0; r < 4; r++)
            effect[(size_t)(b0 + ty * 4 + r) * NH + h] = part[r] + bo;
    }
}

// ============================================================================
extern "C" void kernel_launch(void* const* d_in, const int* in_sizes, int n_in,
                              void* d_out, int out_size)
{
    const float* feat = (const float*)d_in[0];
    const float* act  = (const float*)d_in[1];
    const float* Wq   = (const float*)d_in[2];
    const float* bq   = (const float*)d_in[3];
    const float* Wk   = (const float*)d_in[4];
    const float* bk   = (const float*)d_in[5];
    const float* Wav  = (const float*)d_in[6];
    const float* bav  = (const float*)d_in[7];
    const float* Wfv  = (const float*)d_in[8];
    const float* bfv  = (const float*)d_in[9];
    const float* W1   = (const float*)d_in[10];
    const float* b1   = (const float*)d_in[11];
    const float* W2   = (const float*)d_in[12];
    const float* b2   = (const float*)d_in[13];
    const float* W1o  = (const float*)d_in[14];
    const float* b1o  = (const float*)d_in[15];
    const float* W2o  = (const float*)d_in[16];
    const float* b2o  = (const float*)d_in[17];

    float* out    = (float*)d_out;
    float* effect = out;                    // [B, H]
    float* attnw  = out + BATCH * NH;       // [B, H, D]

    int smem2 = (FED * 128 + DLAT * FED + FED) * 4;
    int smem3 = (128 * 33 + 32 * 132) * 4;
    int smem4 = (DLAT * HID + HID + AED * HID + BT4 * AED + 2 * BT4 * DLAT) * 4;
    int smem5 = (64 * 260 + 2 * KC * HID + HID + HID) * 4;
    cudaFuncSetAttribute(k_gpre, cudaFuncAttributeMaxDynamicSharedMemorySize, smem2);
    cudaFuncSetAttribute(k_mpre, cudaFuncAttributeMaxDynamicSharedMemorySize, smem3);
    cudaFuncSetAttribute(k_pool, cudaFuncAttributeMaxDynamicSharedMemorySize, smem4);
    cudaFuncSetAttribute(k_out,  cudaFuncAttributeMaxDynamicSharedMemorySize, smem5);

    k_prep<<<BATCH, 192>>>(feat, act, Wq, bq, Wk, bk, Wav, bav, attnw);
    k_gpre<<<dim3(2, NH), 256, smem2>>>(Wfv, bfv, W1, b1);
    k_mpre<<<dim3(2, 2, NH), 256, smem3>>>(W2, W1o, b2, b1o);
    k_pool<<<dim3(BATCH / BT4, NH), 256, smem4>>>(feat, W1);
    k_out <<<dim3(BATCH / 64, NH), 256, smem5>>>(W2o, b2o, effect);
}

// round 6
// speedup vs baseline: 1.7884x; 1.3364x over previous
#include <cuda_runtime.h>

#define BATCH 512
#define DLAT  32
#define ACT   18
#define FED   128
#define AED   64
#define VD    192
#define KDIM  192
#define HID   256
#define NH    32

// ---------------- scratch (static device allocations only) ----------------
__device__ __align__(16) float g_w[BATCH * DLAT];
__device__ __align__(16) float g_ae[BATCH * AED];
__device__ __align__(16) float g_G[NH * DLAT * HID];
__device__ __align__(16) float g_c0[NH * HID];
__device__ __align__(16) float g_E[(size_t)NH * BATCH * HID];        // 16MB: ae@W1a per head
__device__ __align__(16) float g_pooled[(size_t)NH * BATCH * HID];   // 16MB
__device__ __align__(16) float g_M[(size_t)NH * HID * HID];          // 8MB: W2@W1o per head
__device__ __align__(16) float g_c1[NH * HID];                       // b2@W1o + b1o

// ---------------- packed f32x2 helpers ----------------
union F2 { float2 f; unsigned long long u; };

__device__ __forceinline__ F2 ffma2(F2 a, F2 b, F2 c) {
    F2 d;
    asm("fma.rn.f32x2 %0, %1, %2, %3;" : "=l"(d.u) : "l"(a.u), "l"(b.u), "l"(c.u));
    return d;
}
__device__ __forceinline__ F2 bcast2(float x) { F2 r; r.f.x = x; r.f.y = x; return r; }
__device__ __forceinline__ F2 lds2(const float* p) { F2 r; r.u = *(const unsigned long long*)p; return r; }
__device__ __forceinline__ F2 zero2() { F2 r; r.f.x = 0.f; r.f.y = 0.f; return r; }

// ============================================================================
// K1: queries, action embeds, scores, softmax, attn_weights.  grid=B, 192 thr
// ============================================================================
__global__ void k_prep(const float* __restrict__ feat, const float* __restrict__ act,
                       const float* __restrict__ Wq,   const float* __restrict__ bq,
                       const float* __restrict__ Wk,   const float* __restrict__ bk,
                       const float* __restrict__ Wav,  const float* __restrict__ bav,
                       float* __restrict__ out_attnw)
{
    int b = blockIdx.x;
    int t = threadIdx.x;
    __shared__ float a_s[ACT];
    __shared__ float q_s[KDIM];
    __shared__ float Wk_s[DLAT * 193];   // pad 193 vs bank conflicts
    __shared__ float p_s[192];
    __shared__ float w_s[DLAT];

    if (t < ACT) a_s[t] = act[b * ACT + t];
#pragma unroll
    for (int r = 0; r < DLAT; r++) Wk_s[r * 193 + t] = Wk[r * KDIM + t];
    __syncthreads();

    float q = bq[t];
#pragma unroll
    for (int i = 0; i < ACT; i++) q = fmaf(a_s[i], Wq[i * KDIM + t], q);
    q_s[t] = q;

    if (t < AED) {
        float e = bav[t];
#pragma unroll
        for (int i = 0; i < ACT; i++) e = fmaf(a_s[i], Wav[i * AED + t], e);
        g_ae[b * AED + t] = e;
    }
    __syncthreads();

    // partial dots: seg = t/32 covers 32 j's for key d = t%32
    {
        int seg = t >> 5, d = t & 31;
        float part = 0.f;
#pragma unroll
        for (int jj = 0; jj < 32; jj++) {
            int j = seg * 32 + jj;
            part = fmaf(Wk_s[d * 193 + j], q_s[j], part);
        }
        p_s[t] = part;
    }
    __syncthreads();

    if (t < 32) {
        float s1 = p_s[t] + p_s[32 + t] + p_s[64 + t] + p_s[96 + t] + p_s[128 + t] + p_s[160 + t];
        // s0 = bk . q  (lane t sums 6 terms, then warp-reduce)
        float s0p = 0.f;
#pragma unroll
        for (int m = 0; m < 6; m++) {
            int j = t * 6 + m;
            s0p = fmaf(bk[j], q_s[j], s0p);
        }
#pragma unroll
        for (int o = 16; o > 0; o >>= 1) s0p += __shfl_xor_sync(0xffffffffu, s0p, o);

        const float inv = 0.07216878364870323f; // 1/sqrt(192)
        float sc = (feat[b * DLAT + t] * s1 + s0p) * inv;
        float m = sc;
#pragma unroll
        for (int o = 16; o > 0; o >>= 1) m = fmaxf(m, __shfl_xor_sync(0xffffffffu, m, o));
        float e = __expf(sc - m);
        float s = e;
#pragma unroll
        for (int o = 16; o > 0; o >>= 1) s += __shfl_xor_sync(0xffffffffu, s, o);
        float w = e / s;
        w_s[t] = w;
        g_w[b * DLAT + t] = w;
    }
    __syncthreads();

    for (int idx = t; idx < NH * DLAT; idx += blockDim.x)
        out_attnw[(size_t)b * NH * DLAT + idx] = w_s[idx & (DLAT - 1)];
}

// ============================================================================
// K2 (merged precompute): 448 blocks, 256 threads, 2 CTAs/SM
//   bx [0,64):    G[h,d,k] = Wfv[d,:]@W1[h,:128,k], c0 = bfv@W1[:128]+b1
//   bx [64,192):  M[h] = W2[h]@W1o[h], c1 = b2@W1o + b1o
//   bx [192,448): E[h,b,k] = ae[b,:]@W1[h,128:,k]
// ============================================================================
__global__ __launch_bounds__(256, 2)
void k_pre2(const float* __restrict__ Wfv, const float* __restrict__ bfv,
            const float* __restrict__ W1,  const float* __restrict__ b1,
            const float* __restrict__ W2,  const float* __restrict__ W1o,
            const float* __restrict__ b2,  const float* __restrict__ b1o)
{
    extern __shared__ float sm[];
    int bx = blockIdx.x;
    int t  = threadIdx.x;

    if (bx < 64) {
        // ---- G + c0: h = bx>>1, d-half = (bx&1)*16; thread t = column k ----
        int h  = bx >> 1;
        int d0 = (bx & 1) * 16;
        float* WfvT = sm;                       // [128 f][36 pad] transposed
        for (int r = 0; r < DLAT; r++) {
            for (int f = t; f < FED; f += 256) WfvT[f * 36 + r] = Wfv[r * FED + f];
        }
        __shared__ float bfv_s[FED];
        if (t < FED) bfv_s[t] = bfv[t];
        __syncthreads();

        const float* W1h = W1 + (size_t)h * VD * HID;
        float acc[16] = {};
        float c0a = (d0 == 0) ? b1[h * HID + t] : 0.f;
#pragma unroll 4
        for (int f = 0; f < FED; f++) {
            float v = W1h[(size_t)f * HID + t];
            if (d0 == 0) c0a = fmaf(bfv_s[f], v, c0a);
            const float* wf = &WfvT[f * 36 + d0];
#pragma unroll
            for (int d = 0; d < 16; d++) acc[d] = fmaf(wf[d], v, acc[d]);
        }
#pragma unroll
        for (int d = 0; d < 16; d++)
            g_G[((size_t)h * DLAT + d0 + d) * HID + t] = acc[d];
        if (d0 == 0) g_c0[h * HID + t] = c0a;

    } else if (bx < 192) {
        // ---- M = W2 @ W1o ----
        int id = bx - 64;
        int kb = (id & 1) * 128;
        int cb = ((id >> 1) & 1) * 128;
        int h  = id >> 2;

        float* As = sm;              // [128][33]
        float* Bs = As + 128 * 33;   // [32][132]
        const float* Ap = W2  + (size_t)h * HID * VD;
        const float* Bp = W1o + (size_t)h * VD * HID;

        int ty = t >> 4, tx = t & 15;
        F2 acc[8][4];
#pragma unroll
        for (int r = 0; r < 8; r++)
#pragma unroll
            for (int j = 0; j < 4; j++) acc[r][j] = zero2();

        for (int vc = 0; vc < VD; vc += 32) {
            __syncthreads();
            {
                int row = t >> 5, col = t & 31;
#pragma unroll
                for (int rr = 0; rr < 16; rr++)
                    As[(row + rr * 8) * 33 + col] = Ap[(size_t)(kb + row + rr * 8) * VD + vc + col];
            }
#pragma unroll
            for (int i = 0; i < 16; i++) {
                int idx = t + i * 256;
                int vr = idx >> 7, col = idx & 127;
                Bs[vr * 132 + col] = Bp[(size_t)(vc + vr) * HID + cb + col];
            }
            __syncthreads();
#pragma unroll
            for (int v = 0; v < 32; v++) {
                F2 bvec[4];
#pragma unroll
                for (int j = 0; j < 4; j++) bvec[j] = lds2(&Bs[v * 132 + tx * 2 + 32 * j]);
#pragma unroll
                for (int r = 0; r < 8; r++) {
                    F2 a2 = bcast2(As[(ty * 8 + r) * 33 + v]);
#pragma unroll
                    for (int j = 0; j < 4; j++) acc[r][j] = ffma2(a2, bvec[j], acc[r][j]);
                }
            }
        }

        float* Mp = g_M + (size_t)h * HID * HID;
#pragma unroll
        for (int r = 0; r < 8; r++)
#pragma unroll
            for (int j = 0; j < 4; j++)
                *(unsigned long long*)&Mp[(size_t)(kb + ty * 8 + r) * HID + cb + tx * 2 + 32 * j] = acc[r][j].u;

        if ((id & 1) == 0 && t < 128) {
            int kp = cb + t;
            float c = b1o[h * HID + kp];
            for (int v = 0; v < VD; v++)
                c = fmaf(b2[h * VD + v], Bp[(size_t)v * HID + kp], c);
            g_c1[h * HID + kp] = c;
        }

    } else {
        // ---- E[h,b,k] = ae[b,:] @ W1[h,128:,k] ----
        int id = bx - 192;
        int b0 = (id & 7) * 64;
        int h  = id >> 3;

        float* ae_s  = sm;                    // [64][64]   16KB
        float* W1a_s = ae_s + 64 * AED;       // [64][256]  64KB

        const float* W1ha = W1 + (size_t)h * VD * HID + (size_t)FED * HID;
        for (int idx = t; idx < AED * HID / 4; idx += 256)
            *(float4*)&W1a_s[idx * 4] = *(const float4*)&W1ha[idx * 4];
        for (int idx = t; idx < 64 * AED / 4; idx += 256)
            *(float4*)&ae_s[idx * 4] = *(const float4*)&g_ae[b0 * AED + idx * 4];
        __syncthreads();

        int tb = t >> 5, tk = t & 31;
        F2 acc[8][4];
#pragma unroll
        for (int r = 0; r < 8; r++)
#pragma unroll
            for (int j = 0; j < 4; j++) acc[r][j] = zero2();

#pragma unroll 2
        for (int a = 0; a < AED; a++) {
            F2 w1a[4];
#pragma unroll
            for (int i = 0; i < 4; i++) w1a[i] = lds2(&W1a_s[a * HID + tk * 2 + 64 * i]);
#pragma unroll
            for (int r = 0; r < 8; r++) {
                F2 av = bcast2(ae_s[(tb * 8 + r) * AED + a]);
#pragma unroll
                for (int i = 0; i < 4; i++) acc[r][i] = ffma2(av, w1a[i], acc[r][i]);
            }
        }

        float* Ep = g_E + ((size_t)h * BATCH + b0) * HID;
#pragma unroll
        for (int r = 0; r < 8; r++)
#pragma unroll
            for (int i = 0; i < 4; i++)
                *(unsigned long long*)&Ep[(tb * 8 + r) * HID + tk * 2 + 64 * i] = acc[r][i].u;
    }
}

// ============================================================================
// K4: pooled[h,b,k] = sum_d w[b,d]*relu( z[b,d]*G[h,d,k] + E[h,b,k] + c0[h,k] )
// grid = (8, 32) = 256 blocks, 256 threads, 2 CTAs/SM (one wave).
// 2 passes over k-halves. Scalar FFMA in d-loop (broadcast mult).
// ============================================================================
__global__ __launch_bounds__(256, 2)
void k_pool(const float* __restrict__ feat)
{
    int h  = blockIdx.y;
    int b0 = blockIdx.x * 64;
    int t  = threadIdx.x;

    extern __shared__ float sm4[];
    float* G_s  = sm4;                 // [32][256]  32KB
    float* zw_s = G_s + DLAT * HID;    // [64][32][2] 16KB (z,w interleaved)
    float* c0_s = zw_s + 64 * 64;      // 256

    for (int idx = t; idx < DLAT * HID / 4; idx += 256)
        *(float4*)&G_s[idx * 4] = *(const float4*)&g_G[(size_t)h * DLAT * HID + idx * 4];
    for (int idx = t; idx < 64 * DLAT; idx += 256) {
        int row = idx >> 5, d = idx & 31;
        zw_s[idx * 2 + 0] = feat[(b0 + row) * DLAT + d];
        zw_s[idx * 2 + 1] = g_w[(b0 + row) * DLAT + d];
    }
    if (t < HID) c0_s[t] = g_c0[h * HID + t];
    __syncthreads();

    int tb = t >> 5, tk = t & 31;
    const float* Ep   = g_E      + ((size_t)h * BATCH + b0 + tb * 8) * HID;
    float*       outp = g_pooled + ((size_t)h * BATCH + b0 + tb * 8) * HID;

#pragma unroll 1
    for (int p = 0; p < 2; p++) {
        int kb = p * 128 + tk * 2;

        float2 cc[2];
#pragma unroll
        for (int i = 0; i < 2; i++) cc[i] = *(const float2*)&c0_s[kb + 64 * i];

        float2 e0[8][2], acc[8][2];
#pragma unroll
        for (int r = 0; r < 8; r++)
#pragma unroll
            for (int i = 0; i < 2; i++) {
                float2 e = *(const float2*)&Ep[r * HID + kb + 64 * i];
                e0[r][i].x = e.x + cc[i].x;
                e0[r][i].y = e.y + cc[i].y;
                acc[r][i].x = 0.f; acc[r][i].y = 0.f;
            }

#pragma unroll 4
        for (int d = 0; d < DLAT; d++) {
            float2 gr[2];
#pragma unroll
            for (int i = 0; i < 2; i++) gr[i] = *(const float2*)&G_s[d * HID + kb + 64 * i];
#pragma unroll
            for (int r = 0; r < 8; r++) {
                float2 zw = *(const float2*)&zw_s[((tb * 8 + r) * DLAT + d) * 2];
#pragma unroll
                for (int i = 0; i < 2; i++) {
                    float ux = fmaf(zw.x, gr[i].x, e0[r][i].x);
                    float uy = fmaf(zw.x, gr[i].y, e0[r][i].y);
                    ux = fmaxf(ux, 0.f);
                    uy = fmaxf(uy, 0.f);
                    acc[r][i].x = fmaf(zw.y, ux, acc[r][i].x);
                    acc[r][i].y = fmaf(zw.y, uy, acc[r][i].y);
                }
            }
        }

#pragma unroll
        for (int r = 0; r < 8; r++)
#pragma unroll
            for (int i = 0; i < 2; i++)
                *(float2*)&outp[r * HID + kb + 64 * i] = acc[r][i];
    }
}

// ============================================================================
// K5: h2 = relu(pooled @ M[h] + c1[h]);  effect[b,h] = h2 . W2o[h] + b2o[h]
// grid = (8, 32), 256 threads, 2 CTAs/SM, double-buffered M chunks.
// ============================================================================
#define KC 16
__global__ __launch_bounds__(256, 2)
void k_out(const float* __restrict__ W2o, const float* __restrict__ b2o,
           float* __restrict__ effect)
{
    int h  = blockIdx.y;
    int b0 = blockIdx.x * 64;
    int t  = threadIdx.x;

    extern __shared__ float sm5[];
    const int PST = 260;
    float* P_s   = sm5;                  // [64][260]
    float* Mb    = P_s + 64 * PST;       // [2][KC][256]
    float* c1_s  = Mb + 2 * KC * HID;    // 256
    float* W2o_s = c1_s + HID;           // 256

    const float* pin = g_pooled + (size_t)h * BATCH * HID + (size_t)b0 * HID;
    for (int idx = t; idx < 64 * 64; idx += 256) {
        int row = idx >> 6, c4 = idx & 63;
        *(float4*)&P_s[row * PST + c4 * 4] = *(const float4*)&pin[row * HID + c4 * 4];
    }
    for (int idx = t; idx < HID; idx += 256) {
        c1_s[idx]  = g_c1[h * HID + idx];
        W2o_s[idx] = W2o[h * HID + idx];
    }
    const float* Mp = g_M + (size_t)h * HID * HID;
    for (int idx = t; idx < KC * 64; idx += 256) {
        int r = idx >> 6, c4 = idx & 63;
        *(float4*)&Mb[r * HID + c4 * 4] = *(const float4*)&Mp[(size_t)r * HID + c4 * 4];
    }
    __syncthreads();

    int ty = t >> 4, tx = t & 15;

    F2 acc[4][8];
#pragma unroll
    for (int r = 0; r < 4; r++)
#pragma unroll
        for (int j = 0; j < 8; j++) acc[r][j] = zero2();

    for (int kc = 0; kc < HID / KC; kc++) {
        float4 pf[4];
        if (kc + 1 < HID / KC) {
#pragma unroll
            for (int i = 0; i < 4; i++) {
                int idx = t + i * 256;
                int r = idx >> 6, c4 = idx & 63;
                pf[i] = *(const float4*)&Mp[(size_t)((kc + 1) * KC + r) * HID + c4 * 4];
            }
        }
        const float* Mc = Mb + (kc & 1) * KC * HID;
#pragma unroll
        for (int kk = 0; kk < KC; kk++) {
            int k = kc * KC + kk;
            F2 mv[8];
#pragma unroll
            for (int j = 0; j < 8; j++) mv[j] = lds2(&Mc[kk * HID + tx * 2 + 32 * j]);
#pragma unroll
            for (int r = 0; r < 4; r++) {
                F2 p2 = bcast2(P_s[(ty * 4 + r) * PST + k]);
#pragma unroll
                for (int j = 0; j < 8; j++) acc[r][j] = ffma2(p2, mv[j], acc[r][j]);
            }
        }
        if (kc + 1 < HID / KC) {
            float* dst = Mb + ((kc + 1) & 1) * KC * HID;
#pragma unroll
            for (int i = 0; i < 4; i++) {
                int idx = t + i * 256;
                int r = idx >> 6, c4 = idx & 63;
                *(float4*)&dst[r * HID + c4 * 4] = pf[i];
            }
        }
        __syncthreads();
    }

    float part[4];
#pragma unroll
    for (int r = 0; r < 4; r++) {
        float s = 0.f;
#pragma unroll
        for (int j = 0; j < 8; j++) {
            int c = tx * 2 + 32 * j;
            float hx = fmaxf(acc[r][j].f.x + c1_s[c], 0.f);
            float hy = fmaxf(acc[r][j].f.y + c1_s[c + 1], 0.f);
            s = fmaf(hx, W2o_s[c], s);
            s = fmaf(hy, W2o_s[c + 1], s);
        }
        part[r] = s;
    }
#pragma unroll
    for (int o = 8; o > 0; o >>= 1)
#pragma unroll
        for (int r = 0; r < 4; r++)
            part[r] += __shfl_xor_sync(0xffffffffu, part[r], o);

    if (tx == 0) {
        float bo = b2o[h];
#pragma unroll
        for (int r = 0; r < 4; r++)
            effect[(size_t)(b0 + ty * 4 + r) * NH + h] = part[r] + bo;
    }
}

// ============================================================================
extern "C" void kernel_launch(void* const* d_in, const int* in_sizes, int n_in,
                              void* d_out, int out_size)
{
    const float* feat = (const float*)d_in[0];
    const float* act  = (const float*)d_in[1];
    const float* Wq   = (const float*)d_in[2];
    const float* bq   = (const float*)d_in[3];
    const float* Wk   = (const float*)d_in[4];
    const float* bk   = (const float*)d_in[5];
    const float* Wav  = (const float*)d_in[6];
    const float* bav  = (const float*)d_in[7];
    const float* Wfv  = (const float*)d_in[8];
    const float* bfv  = (const float*)d_in[9];
    const float* W1   = (const float*)d_in[10];
    const float* b1   = (const float*)d_in[11];
    const float* W2   = (const float*)d_in[12];
    const float* b2   = (const float*)d_in[13];
    const float* W1o  = (const float*)d_in[14];
    const float* b1o  = (const float*)d_in[15];
    const float* W2o  = (const float*)d_in[16];
    const float* b2o  = (const float*)d_in[17];

    float* out    = (float*)d_out;
    float* effect = out;                    // [B, H]
    float* attnw  = out + BATCH * NH;       // [B, H, D]

    int smem2 = (AED * HID + 64 * AED) * 4;              // 80KB (eg branch = max)
    int smem4 = (DLAT * HID + 64 * 64 + HID) * 4;        // 49.25KB
    int smem5 = (64 * 260 + 2 * KC * HID + HID + HID) * 4;
    cudaFuncSetAttribute(k_pre2, cudaFuncAttributeMaxDynamicSharedMemorySize, smem2);
    cudaFuncSetAttribute(k_pool, cudaFuncAttributeMaxDynamicSharedMemorySize, smem4);
    cudaFuncSetAttribute(k_out,  cudaFuncAttributeMaxDynamicSharedMemorySize, smem5);

    k_prep<<<BATCH, 192>>>(feat, act, Wq, bq, Wk, bk, Wav, bav, attnw);
    k_pre2<<<448, 256, smem2>>>(Wfv, bfv, W1, b1, W2, W1o, b2, b1o);   // 64 G + 128 M + 256 E
    k_pool<<<dim3(BATCH / 64, NH), 256, smem4>>>(feat);
    k_out <<<dim3(BATCH / 64, NH), 256, smem5>>>(W2o, b2o, effect);
}

// round 7
// speedup vs baseline: 1.9786x; 1.1064x over previous
#include <cuda_runtime.h>

#define BATCH 512
#define DLAT  32
#define ACT   18
#define FED   128
#define AED   64
#define VD    192
#define KDIM  192
#define HID   256
#define NH    32

// ---------------- scratch (static device allocations only) ----------------
__device__ __align__(16) float g_w[BATCH * DLAT];
__device__ __align__(16) float g_ae[BATCH * AED];
__device__ __align__(16) float g_G[NH * DLAT * HID];
__device__ __align__(16) float g_c0[NH * HID];
__device__ __align__(16) float g_E[(size_t)NH * BATCH * HID];        // 16MB: ae@W1a per head
__device__ __align__(16) float g_M[(size_t)NH * HID * HID];          // 8MB: W2@W1o per head
__device__ __align__(16) float g_c1[NH * HID];                       // b2@W1o + b1o

// ---------------- packed f32x2 helpers ----------------
union F2 { float2 f; unsigned long long u; };

__device__ __forceinline__ F2 ffma2(F2 a, F2 b, F2 c) {
    F2 d;
    asm("fma.rn.f32x2 %0, %1, %2, %3;" : "=l"(d.u) : "l"(a.u), "l"(b.u), "l"(c.u));
    return d;
}
__device__ __forceinline__ F2 bcast2(float x) { F2 r; r.f.x = x; r.f.y = x; return r; }
__device__ __forceinline__ F2 lds2(const float* p) { F2 r; r.u = *(const unsigned long long*)p; return r; }
__device__ __forceinline__ F2 zero2() { F2 r; r.f.x = 0.f; r.f.y = 0.f; return r; }

// ============================================================================
// K1: queries, action embeds, scores, softmax, attn_weights.  grid=B, 192 thr
// ============================================================================
__global__ void k_prep(const float* __restrict__ feat, const float* __restrict__ act,
                       const float* __restrict__ Wq,   const float* __restrict__ bq,
                       const float* __restrict__ Wk,   const float* __restrict__ bk,
                       const float* __restrict__ Wav,  const float* __restrict__ bav,
                       float* __restrict__ out_attnw)
{
    int b = blockIdx.x;
    int t = threadIdx.x;
    __shared__ float a_s[ACT];
    __shared__ float q_s[KDIM];
    __shared__ float Wk_s[DLAT * 193];   // pad 193 vs bank conflicts
    __shared__ float p_s[192];
    __shared__ float w_s[DLAT];

    if (t < ACT) a_s[t] = act[b * ACT + t];
#pragma unroll
    for (int r = 0; r < DLAT; r++) Wk_s[r * 193 + t] = Wk[r * KDIM + t];
    __syncthreads();

    float q = bq[t];
#pragma unroll
    for (int i = 0; i < ACT; i++) q = fmaf(a_s[i], Wq[i * KDIM + t], q);
    q_s[t] = q;

    if (t < AED) {
        float e = bav[t];
#pragma unroll
        for (int i = 0; i < ACT; i++) e = fmaf(a_s[i], Wav[i * AED + t], e);
        g_ae[b * AED + t] = e;
    }
    __syncthreads();

    {
        int seg = t >> 5, d = t & 31;
        float part = 0.f;
#pragma unroll
        for (int jj = 0; jj < 32; jj++) {
            int j = seg * 32 + jj;
            part = fmaf(Wk_s[d * 193 + j], q_s[j], part);
        }
        p_s[t] = part;
    }
    __syncthreads();

    if (t < 32) {
        float s1 = p_s[t] + p_s[32 + t] + p_s[64 + t] + p_s[96 + t] + p_s[128 + t] + p_s[160 + t];
        float s0p = 0.f;
#pragma unroll
        for (int m = 0; m < 6; m++) {
            int j = t * 6 + m;
            s0p = fmaf(bk[j], q_s[j], s0p);
        }
#pragma unroll
        for (int o = 16; o > 0; o >>= 1) s0p += __shfl_xor_sync(0xffffffffu, s0p, o);

        const float inv = 0.07216878364870323f; // 1/sqrt(192)
        float sc = (feat[b * DLAT + t] * s1 + s0p) * inv;
        float m = sc;
#pragma unroll
        for (int o = 16; o > 0; o >>= 1) m = fmaxf(m, __shfl_xor_sync(0xffffffffu, m, o));
        float e = __expf(sc - m);
        float s = e;
#pragma unroll
        for (int o = 16; o > 0; o >>= 1) s += __shfl_xor_sync(0xffffffffu, s, o);
        float w = e / s;
        w_s[t] = w;
        g_w[b * DLAT + t] = w;
    }
    __syncthreads();

    for (int idx = t; idx < NH * DLAT; idx += blockDim.x)
        out_attnw[(size_t)b * NH * DLAT + idx] = w_s[idx & (DLAT - 1)];
}

// ============================================================================
// K2 (merged precompute): 448 blocks, 256 threads, 2 CTAs/SM
//   bx [0,64):    G[h,d,k] = Wfv[d,:]@W1[h,:128,k], c0 = bfv@W1[:128]+b1
//   bx [64,192):  M[h] = W2[h]@W1o[h], c1 = b2@W1o + b1o
//   bx [192,448): E[h,b,k] = ae[b,:]@W1[h,128:,k]
// ============================================================================
__global__ __launch_bounds__(256, 2)
void k_pre2(const float* __restrict__ Wfv, const float* __restrict__ bfv,
            const float* __restrict__ W1,  const float* __restrict__ b1,
            const float* __restrict__ W2,  const float* __restrict__ W1o,
            const float* __restrict__ b2,  const float* __restrict__ b1o)
{
    extern __shared__ float sm[];
    int bx = blockIdx.x;
    int t  = threadIdx.x;

    if (bx < 64) {
        int h  = bx >> 1;
        int d0 = (bx & 1) * 16;
        float* WfvT = sm;                       // [128 f][36 pad] transposed
        for (int r = 0; r < DLAT; r++) {
            for (int f = t; f < FED; f += 256) WfvT[f * 36 + r] = Wfv[r * FED + f];
        }
        __shared__ float bfv_s[FED];
        if (t < FED) bfv_s[t] = bfv[t];
        __syncthreads();

        const float* W1h = W1 + (size_t)h * VD * HID;
        float acc[16] = {};
        float c0a = (d0 == 0) ? b1[h * HID + t] : 0.f;
#pragma unroll 4
        for (int f = 0; f < FED; f++) {
            float v = W1h[(size_t)f * HID + t];
            if (d0 == 0) c0a = fmaf(bfv_s[f], v, c0a);
            const float* wf = &WfvT[f * 36 + d0];
#pragma unroll
            for (int d = 0; d < 16; d++) acc[d] = fmaf(wf[d], v, acc[d]);
        }
#pragma unroll
        for (int d = 0; d < 16; d++)
            g_G[((size_t)h * DLAT + d0 + d) * HID + t] = acc[d];
        if (d0 == 0) g_c0[h * HID + t] = c0a;

    } else if (bx < 192) {
        int id = bx - 64;
        int kb = (id & 1) * 128;
        int cb = ((id >> 1) & 1) * 128;
        int h  = id >> 2;

        float* As = sm;              // [128][33]
        float* Bs = As + 128 * 33;   // [32][132]
        const float* Ap = W2  + (size_t)h * HID * VD;
        const float* Bp = W1o + (size_t)h * VD * HID;

        int ty = t >> 4, tx = t & 15;
        F2 acc[8][4];
#pragma unroll
        for (int r = 0; r < 8; r++)
#pragma unroll
            for (int j = 0; j < 4; j++) acc[r][j] = zero2();

        for (int vc = 0; vc < VD; vc += 32) {
            __syncthreads();
            {
                int row = t >> 5, col = t & 31;
#pragma unroll
                for (int rr = 0; rr < 16; rr++)
                    As[(row + rr * 8) * 33 + col] = Ap[(size_t)(kb + row + rr * 8) * VD + vc + col];
            }
#pragma unroll
            for (int i = 0; i < 16; i++) {
                int idx = t + i * 256;
                int vr = idx >> 7, col = idx & 127;
                Bs[vr * 132 + col] = Bp[(size_t)(vc + vr) * HID + cb + col];
            }
            __syncthreads();
#pragma unroll
            for (int v = 0; v < 32; v++) {
                F2 bvec[4];
#pragma unroll
                for (int j = 0; j < 4; j++) bvec[j] = lds2(&Bs[v * 132 + tx * 2 + 32 * j]);
#pragma unroll
                for (int r = 0; r < 8; r++) {
                    F2 a2 = bcast2(As[(ty * 8 + r) * 33 + v]);
#pragma unroll
                    for (int j = 0; j < 4; j++) acc[r][j] = ffma2(a2, bvec[j], acc[r][j]);
                }
            }
        }

        float* Mp = g_M + (size_t)h * HID * HID;
#pragma unroll
        for (int r = 0; r < 8; r++)
#pragma unroll
            for (int j = 0; j < 4; j++)
                *(unsigned long long*)&Mp[(size_t)(kb + ty * 8 + r) * HID + cb + tx * 2 + 32 * j] = acc[r][j].u;

        if ((id & 1) == 0 && t < 128) {
            int kp = cb + t;
            float c = b1o[h * HID + kp];
            for (int v = 0; v < VD; v++)
                c = fmaf(b2[h * VD + v], Bp[(size_t)v * HID + kp], c);
            g_c1[h * HID + kp] = c;
        }

    } else {
        int id = bx - 192;
        int b0 = (id & 7) * 64;
        int h  = id >> 3;

        float* ae_s  = sm;                    // [64][64]   16KB
        float* W1a_s = ae_s + 64 * AED;       // [64][256]  64KB

        const float* W1ha = W1 + (size_t)h * VD * HID + (size_t)FED * HID;
        for (int idx = t; idx < AED * HID / 4; idx += 256)
            *(float4*)&W1a_s[idx * 4] = *(const float4*)&W1ha[idx * 4];
        for (int idx = t; idx < 64 * AED / 4; idx += 256)
            *(float4*)&ae_s[idx * 4] = *(const float4*)&g_ae[b0 * AED + idx * 4];
        __syncthreads();

        int tb = t >> 5, tk = t & 31;
        F2 acc[8][4];
#pragma unroll
        for (int r = 0; r < 8; r++)
#pragma unroll
            for (int j = 0; j < 4; j++) acc[r][j] = zero2();

#pragma unroll 2
        for (int a = 0; a < AED; a++) {
            F2 w1a[4];
#pragma unroll
            for (int i = 0; i < 4; i++) w1a[i] = lds2(&W1a_s[a * HID + tk * 2 + 64 * i]);
#pragma unroll
            for (int r = 0; r < 8; r++) {
                F2 av = bcast2(ae_s[(tb * 8 + r) * AED + a]);
#pragma unroll
                for (int i = 0; i < 4; i++) acc[r][i] = ffma2(av, w1a[i], acc[r][i]);
            }
        }

        float* Ep = g_E + ((size_t)h * BATCH + b0) * HID;
#pragma unroll
        for (int r = 0; r < 8; r++)
#pragma unroll
            for (int i = 0; i < 4; i++)
                *(unsigned long long*)&Ep[(tb * 8 + r) * HID + tk * 2 + 64 * i] = acc[r][i].u;
    }
}

// ============================================================================
// K3 (fused pool+out): grid (8, 32), 128 threads, 2 CTAs/SM.
// Phase 1 (pool): P[b,k] = sum_d w*relu(z*G + E + c0) -> smem only.
// Phase 2 (out):  h2 = relu(P @ M + c1); effect = h2 . W2o + b2o.
// smem overlay: [P 64KB][G<->Mb 32KB][zw<->c1/W2o 16KB][c0 1KB] = 115712B
// ============================================================================
__global__ __launch_bounds__(128, 2)
void k_fused(const float* __restrict__ feat,
             const float* __restrict__ W2o, const float* __restrict__ b2o,
             float* __restrict__ effect)
{
    int h  = blockIdx.y;
    int b0 = blockIdx.x * 64;
    int t  = threadIdx.x;
    int tb = t >> 4, tk = t & 15;     // tb: 8 row-groups, tk: 16 col lanes

    extern __shared__ float sm[];
    float* P_s  = sm;                 // [64][256]   65536B
    float* GM   = sm + 64 * 256;      // 8192 floats: G (ph1) / Mb x2 (ph2)
    float* AUX  = GM + 8192;          // 4096 floats: zw (ph1) / c1+W2o (ph2)
    float* c0_s = AUX + 4096;         // 256 floats

    // ---- phase 1 loads ----
    for (int i = 0; i < 16; i++)      // G: 32*256 floats = 2048 float4
        ((float4*)GM)[t + i * 128] = ((const float4*)(g_G + (size_t)h * DLAT * HID))[t + i * 128];
    for (int idx = t; idx < 64 * DLAT; idx += 128) {
        int row = idx >> 5, d = idx & 31;
        AUX[idx * 2 + 0] = feat[(b0 + row) * DLAT + d];
        AUX[idx * 2 + 1] = g_w[(b0 + row) * DLAT + d];
    }
    for (int idx = t; idx < HID; idx += 128) c0_s[idx] = g_c0[h * HID + idx];
    __syncthreads();

    const float* Ep = g_E + ((size_t)h * BATCH + b0 + tb * 8) * HID;

    // ---- phase 1: 4 column passes of 64 cols (each thread 2 F2 per row) ----
#pragma unroll 1
    for (int p = 0; p < 4; p++) {
        int cb = p * 64 + tk * 2;
        float2 cc[2];
#pragma unroll
        for (int i = 0; i < 2; i++) cc[i] = *(const float2*)&c0_s[cb + 32 * i];

        float2 e0[8][2], acc[8][2];
#pragma unroll
        for (int r = 0; r < 8; r++)
#pragma unroll
            for (int i = 0; i < 2; i++) {
                float2 e = *(const float2*)&Ep[r * HID + cb + 32 * i];
                e0[r][i].x = e.x + cc[i].x;
                e0[r][i].y = e.y + cc[i].y;
                acc[r][i].x = 0.f; acc[r][i].y = 0.f;
            }

#pragma unroll 4
        for (int d = 0; d < DLAT; d++) {
            float2 gr[2];
#pragma unroll
            for (int i = 0; i < 2; i++) gr[i] = *(const float2*)&GM[d * HID + cb + 32 * i];
#pragma unroll
            for (int r = 0; r < 8; r++) {
                float2 zw = *(const float2*)&AUX[((tb * 8 + r) * DLAT + d) * 2];
#pragma unroll
                for (int i = 0; i < 2; i++) {
                    float ux = fmaf(zw.x, gr[i].x, e0[r][i].x);
                    float uy = fmaf(zw.x, gr[i].y, e0[r][i].y);
                    ux = fmaxf(ux, 0.f);
                    uy = fmaxf(uy, 0.f);
                    acc[r][i].x = fmaf(zw.y, ux, acc[r][i].x);
                    acc[r][i].y = fmaf(zw.y, uy, acc[r][i].y);
                }
            }
        }

#pragma unroll
        for (int r = 0; r < 8; r++)
#pragma unroll
            for (int i = 0; i < 2; i++)
                *(float2*)&P_s[(tb * 8 + r) * HID + cb + 32 * i] = acc[r][i];
    }
    __syncthreads();   // phase 1 done: GM/AUX free, P_s complete

    // ---- phase 2 loads: c1 + W2o into AUX, Mb chunk 0 into GM ----
    for (int idx = t; idx < HID; idx += 128) {
        AUX[idx]       = g_c1[h * HID + idx];
        AUX[HID + idx] = W2o[h * HID + idx];
    }
    const float* Mp = g_M + (size_t)h * HID * HID;
#pragma unroll
    for (int i = 0; i < 8; i++)       // 16*256 floats = 1024 float4
        ((float4*)GM)[t + i * 128] = ((const float4*)Mp)[t + i * 128];
    __syncthreads();

    // ---- phase 2: GEMM P[64,256] @ M[256,256], 16 k-chunks, dbl-buffered ----
    F2 acc[8][8];
#pragma unroll
    for (int r = 0; r < 8; r++)
#pragma unroll
        for (int j = 0; j < 8; j++) acc[r][j] = zero2();

#pragma unroll 1
    for (int kc = 0; kc < 16; kc++) {
        float4 pf[8];
        if (kc < 15) {
#pragma unroll
            for (int i = 0; i < 8; i++)
                pf[i] = ((const float4*)(Mp + (size_t)(kc + 1) * 16 * HID))[t + i * 128];
        }
        const float* Mc = GM + (kc & 1) * 4096;
#pragma unroll
        for (int kk = 0; kk < 16; kk++) {
            int k = kc * 16 + kk;
            F2 mv[8];
#pragma unroll
            for (int j = 0; j < 8; j++) mv[j] = lds2(&Mc[kk * HID + tk * 2 + 32 * j]);
#pragma unroll
            for (int r = 0; r < 8; r++) {
                F2 p2 = bcast2(P_s[(tb * 8 + r) * HID + k]);
#pragma unroll
                for (int j = 0; j < 8; j++) acc[r][j] = ffma2(p2, mv[j], acc[r][j]);
            }
        }
        if (kc < 15) {
            float* dst = GM + ((kc + 1) & 1) * 4096;
#pragma unroll
            for (int i = 0; i < 8; i++)
                ((float4*)dst)[t + i * 128] = pf[i];
        }
        __syncthreads();
    }

    // ---- epilogue: +c1, relu, dot W2o, reduce over tk (16 lanes) ----
    float part[8];
#pragma unroll
    for (int r = 0; r < 8; r++) {
        float s = 0.f;
#pragma unroll
        for (int j = 0; j < 8; j++) {
            int c = tk * 2 + 32 * j;
            float hx = fmaxf(acc[r][j].f.x + AUX[c], 0.f);
            float hy = fmaxf(acc[r][j].f.y + AUX[c + 1], 0.f);
            s = fmaf(hx, AUX[HID + c], s);
            s = fmaf(hy, AUX[HID + c + 1], s);
        }
        part[r] = s;
    }
#pragma unroll
    for (int o = 8; o > 0; o >>= 1)
#pragma unroll
        for (int r = 0; r < 8; r++)
            part[r] += __shfl_xor_sync(0xffffffffu, part[r], o);

    if (tk == 0) {
        float bo = b2o[h];
#pragma unroll
        for (int r = 0; r < 8; r++)
            effect[(size_t)(b0 + tb * 8 + r) * NH + h] = part[r] + bo;
    }
}

// ============================================================================
extern "C" void kernel_launch(void* const* d_in, const int* in_sizes, int n_in,
                              void* d_out, int out_size)
{
    const float* feat = (const float*)d_in[0];
    const float* act  = (const float*)d_in[1];
    const float* Wq   = (const float*)d_in[2];
    const float* bq   = (const float*)d_in[3];
    const float* Wk   = (const float*)d_in[4];
    const float* bk   = (const float*)d_in[5];
    const float* Wav  = (const float*)d_in[6];
    const float* bav  = (const float*)d_in[7];
    const float* Wfv  = (const float*)d_in[8];
    const float* bfv  = (const float*)d_in[9];
    const float* W1   = (const float*)d_in[10];
    const float* b1   = (const float*)d_in[11];
    const float* W2   = (const float*)d_in[12];
    const float* b2   = (const float*)d_in[13];
    const float* W1o  = (const float*)d_in[14];
    const float* b1o  = (const float*)d_in[15];
    const float* W2o  = (const float*)d_in[16];
    const float* b2o  = (const float*)d_in[17];

    float* out    = (float*)d_out;
    float* effect = out;                    // [B, H]
    float* attnw  = out + BATCH * NH;       // [B, H, D]

    int smem2 = (AED * HID + 64 * AED) * 4;                      // 80KB
    int smem3 = (64 * 256 + 8192 + 4096 + 256) * 4;              // 115712B
    cudaFuncSetAttribute(k_pre2,  cudaFuncAttributeMaxDynamicSharedMemorySize, smem2);
    cudaFuncSetAttribute(k_fused, cudaFuncAttributeMaxDynamicSharedMemorySize, smem3);

    k_prep<<<BATCH, 192>>>(feat, act, Wq, bq, Wk, bk, Wav, bav, attnw);
    k_pre2<<<448, 256, smem2>>>(Wfv, bfv, W1, b1, W2, W1o, b2, b1o);   // 64 G + 128 M + 256 E
    k_fused<<<dim3(BATCH / 64, NH), 128, smem3>>>(feat, W2o, b2o, effect);
}